// round 16
// baseline (speedup 1.0000x reference)
#include <cuda_runtime.h>
#include <cstdint>
#include <math.h>

#define T_  512
#define B_  32
#define H_  1024
#define BH  32768
#define OUTMAIN 16777216  // T*B*H

// ---- scratch (device globals; allocation-free rule) ----
__device__ float g_gx[(size_t)T_ * B_ * 4096];  // [T*B][4H] input-projection gates
__device__ float g_out0[(size_t)T_ * BH];       // layer-0 outputs [t][b][n]
__device__ float g_h[(size_t)(T_ + 1) * BH];    // UNIQUE per-step transposed h: [t][n][b]
__device__ float g_c[2][BH];                    // final cell state per layer [b*H + n]
__device__ unsigned g_grp[8 * 32];              // tree barrier: 8 group counters (128B apart)
__device__ unsigned g_root;                     // tree barrier: root counter

// ---- f32x2 helpers ----
__device__ __forceinline__ unsigned long long pack2(float x) {
    unsigned u = __float_as_uint(x);
    unsigned long long r;
    asm("mov.b64 %0, {%1, %1};" : "=l"(r) : "r"(u));
    return r;
}
__device__ __forceinline__ void ffma2(unsigned long long& d, unsigned long long a,
                                      unsigned long long b) {
    asm("fma.rn.f32x2 %0, %1, %2, %0;" : "+l"(d) : "l"(a), "l"(b));
}
__device__ __forceinline__ float2 unpack2(unsigned long long v) {
    return make_float2(__uint_as_float((unsigned)v), __uint_as_float((unsigned)(v >> 32)));
}
// fast, overflow-safe pointwise (MUFU path)
__device__ __forceinline__ float sigm(float x) { return 1.0f / (1.0f + __expf(-x)); }
__device__ __forceinline__ float tanh_fast(float x) {
    return 1.0f - 2.0f / (__expf(2.0f * x) + 1.0f);   // e=inf -> 1, e=0 -> -1
}

// ---- gpu-scope release/acquire primitives ----
__device__ __forceinline__ void red_release(unsigned* p) {
    asm volatile("red.release.gpu.global.add.u32 [%0], %1;" :: "l"(p), "r"(1u) : "memory");
}
__device__ __forceinline__ unsigned ld_acquire(const unsigned* p) {
    unsigned v;
    asm volatile("ld.acquire.gpu.global.u32 %0, [%1];" : "=r"(v) : "l"(p) : "memory");
    return v;
}

__global__ void zero_cnt() {
    if (threadIdx.x < 8) g_grp[threadIdx.x * 32] = 0u;
    if (threadIdx.x == 8) g_root = 0u;
}

// ================= input-projection GEMM (128x128 tile, 8x8/thread; proven) =================
// g_gx[r][c] = sum_d A[r][d]*Wih[c][d] + bih[c] + bhh[c],  r = t*B + b
// xlayout=1: A is x[B,T,I] (row r -> x[b][t]); xlayout=0: A = g_out0 row-major.
__global__ void __launch_bounds__(256, 2) gx_gemm(const float* __restrict__ A,
                                                  const float* __restrict__ Wih,
                                                  const float* __restrict__ bih,
                                                  const float* __restrict__ bhh,
                                                  int xlayout) {
    __shared__ __align__(16) float As[32][132];
    __shared__ __align__(16) float Ws[32][132];
    const int tid = threadIdx.x;
    const int rowTile = blockIdx.y * 128, colTile = blockIdx.x * 128;
    const int kq = tid & 7;
    const int rr = tid >> 3;
    const int r0 = (tid >> 4) * 8;
    const int c0 = (tid & 15) * 8;
    const float* Asrc = xlayout ? A : g_out0;

    unsigned long long acc[4][8];
#pragma unroll
    for (int i = 0; i < 4; i++)
#pragma unroll
        for (int j = 0; j < 8; j++) acc[i][j] = 0ull;

    for (int kc = 0; kc < 1024; kc += 32) {
#pragma unroll
        for (int it = 0; it < 4; it++) {
            int r = rr + it * 32;
            int R = rowTile + r;
            size_t base = xlayout ? ((size_t)(R & 31) * 512 + (size_t)(R >> 5)) * 1024
                                  : (size_t)R * 1024;
            float4 v = *(const float4*)(Asrc + base + kc + kq * 4);
            As[kq * 4 + 0][r] = v.x; As[kq * 4 + 1][r] = v.y;
            As[kq * 4 + 2][r] = v.z; As[kq * 4 + 3][r] = v.w;
        }
#pragma unroll
        for (int it = 0; it < 4; it++) {
            int c = rr + it * 32;
            float4 v = *(const float4*)(Wih + (size_t)(colTile + c) * 1024 + kc + kq * 4);
            Ws[kq * 4 + 0][c] = v.x; Ws[kq * 4 + 1][c] = v.y;
            Ws[kq * 4 + 2][c] = v.z; Ws[kq * 4 + 3][c] = v.w;
        }
        __syncthreads();
#pragma unroll
        for (int k = 0; k < 32; k++) {
            ulonglong2 a01 = *(const ulonglong2*)&As[k][r0];
            ulonglong2 a23 = *(const ulonglong2*)&As[k][r0 + 4];
            float4 w0 = *(const float4*)&Ws[k][c0];
            float4 w1 = *(const float4*)&Ws[k][c0 + 4];
            float wj[8] = {w0.x, w0.y, w0.z, w0.w, w1.x, w1.y, w1.z, w1.w};
#pragma unroll
            for (int j = 0; j < 8; j++) {
                unsigned long long wd = pack2(wj[j]);
                ffma2(acc[0][j], a01.x, wd);
                ffma2(acc[1][j], a01.y, wd);
                ffma2(acc[2][j], a23.x, wd);
                ffma2(acc[3][j], a23.y, wd);
            }
        }
        __syncthreads();
    }

    float4 b0v = *(const float4*)(bih + colTile + c0);
    float4 b1v = *(const float4*)(bih + colTile + c0 + 4);
    float4 h0v = *(const float4*)(bhh + colTile + c0);
    float4 h1v = *(const float4*)(bhh + colTile + c0 + 4);
    float bias[8] = {b0v.x + h0v.x, b0v.y + h0v.y, b0v.z + h0v.z, b0v.w + h0v.w,
                     b1v.x + h1v.x, b1v.y + h1v.y, b1v.z + h1v.z, b1v.w + h1v.w};
#pragma unroll
    for (int rp = 0; rp < 4; rp++) {
        float lo[8], hi[8];
#pragma unroll
        for (int j = 0; j < 8; j++) {
            float2 v = unpack2(acc[rp][j]);
            lo[j] = v.x + bias[j];
            hi[j] = v.y + bias[j];
        }
        size_t r = rowTile + r0 + rp * 2;
        *(float4*)(g_gx + r * 4096 + colTile + c0)           = make_float4(lo[0], lo[1], lo[2], lo[3]);
        *(float4*)(g_gx + r * 4096 + colTile + c0 + 4)       = make_float4(lo[4], lo[5], lo[6], lo[7]);
        *(float4*)(g_gx + (r + 1) * 4096 + colTile + c0)     = make_float4(hi[0], hi[1], hi[2], hi[3]);
        *(float4*)(g_gx + (r + 1) * 4096 + colTile + c0 + 4) = make_float4(hi[4], hi[5], hi[6], hi[7]);
    }
}

// ================= persistent recurrence (one layer, 512 steps) =================
// 128 blocks x 512 threads. Block owns hidden units [blk*8, blk*8+8), all 4 gates,
// all 32 batches. W_hh slice in SMEM. h via unique per-step buffers g_h[t][n][b].
// Inter-step sync: 2-level release/acquire RED tree (8 groups of 16 -> root).
#define WROW 1028  // padded SMEM row stride (floats)
__global__ void __launch_bounds__(512, 1) lstm_persist(float* __restrict__ dout,
                                                       const float* __restrict__ Whh,
                                                       int layer, unsigned baseStep) {
    extern __shared__ float sm[];
    float* sW = sm;                                    // [32][WROW]
    float4* red = (float4*)(sm + 32 * WROW);           // [16][256] float4

    const int tid = threadIdx.x;
    const int blk = blockIdx.x;
    const int grp = blk >> 4;             // 8 groups of 16 blocks
    const bool leader = (blk & 15) == 0;  // one leader per group

    // ---- stage W: sW row (g*8+u) = Whh[g*1024 + blk*8 + u][0..1024) ----
    for (int i = tid; i < 8192; i += 512) {
        int row = i >> 8;
        int q   = i & 255;
        int srcRow = (row >> 3) * 1024 + blk * 8 + (row & 7);
        float4 v = *(const float4*)(Whh + (size_t)srcRow * 1024 + q * 4);
        *(float4*)(sW + (size_t)row * WROW + q * 4) = v;
    }
    __syncthreads();

    // matmul identity: 16 k-slices x 32 (unit, batch-group) threads
    const int ks = tid >> 5;
    const int u  = tid & 31;
    const int nl = u & 7;
    const int b0 = (u >> 3) * 8;
    const int k0 = ks * 64;
    // pointwise identity (tid < 256): (batch pb, unit pn)
    const int pb = tid >> 3, pn = tid & 7;
    const int n2 = blk * 8 + pn;
    float c = 0.f;
    float* outbuf = (layer == 0) ? g_out0 : dout;

    // preload gx for t=0
    float pg0 = 0.f, pg1 = 0.f, pg2 = 0.f, pg3 = 0.f;
    if (tid < 256) {
        const float* gxr = g_gx + (size_t)pb * 4096;
        pg0 = gxr[n2]; pg1 = gxr[1024 + n2]; pg2 = gxr[2048 + n2]; pg3 = gxr[3072 + n2];
    }

    for (int t = 0; t < 512; t++) {
        float gi = pg0, gf = pg1, gg_ = pg2, go = pg3;

        if (t > 0) {
            const float* hprev = g_h + (size_t)t * BH;
            unsigned long long acc[4][4];
#pragma unroll
            for (int g = 0; g < 4; g++)
#pragma unroll
                for (int p = 0; p < 4; p++) acc[g][p] = 0ull;

            for (int kk = 0; kk < 64; kk += 4) {
                int k = k0 + kk;
                float4 wv[4];
#pragma unroll
                for (int g = 0; g < 4; g++)
                    wv[g] = *(const float4*)(sW + (size_t)(g * 8 + nl) * WROW + k);
#pragma unroll
                for (int q = 0; q < 4; q++) {
                    const ulonglong2* hp = (const ulonglong2*)(hprev + (size_t)(k + q) * 32 + b0);
                    ulonglong2 hA = hp[0];
                    ulonglong2 hB = hp[1];
#pragma unroll
                    for (int g = 0; g < 4; g++) {
                        unsigned long long wd = pack2(((const float*)&wv[g])[q]);
                        ffma2(acc[g][0], hA.x, wd);
                        ffma2(acc[g][1], hA.y, wd);
                        ffma2(acc[g][2], hB.x, wd);
                        ffma2(acc[g][3], hB.y, wd);
                    }
                }
            }
#pragma unroll
            for (int p = 0; p < 4; p++) {
                float2 s0 = unpack2(acc[0][p]);
                float2 s1 = unpack2(acc[1][p]);
                float2 s2 = unpack2(acc[2][p]);
                float2 s3 = unpack2(acc[3][p]);
                red[ks * 256 + (b0 + p * 2 + 0) * 8 + nl] = make_float4(s0.x, s1.x, s2.x, s3.x);
                red[ks * 256 + (b0 + p * 2 + 1) * 8 + nl] = make_float4(s0.y, s1.y, s2.y, s3.y);
            }
        }
        __syncthreads();

        if (tid < 256) {
            if (t > 0) {
#pragma unroll
                for (int s = 0; s < 16; s++) {
                    float4 r = red[s * 256 + tid];
                    gi += r.x; gf += r.y; gg_ += r.z; go += r.w;
                }
            }
            float c1 = sigm(gf) * c + sigm(gi) * tanh_fast(gg_);
            float h1 = sigm(go) * tanh_fast(c1);
            c = c1;
            if (t < 511) g_h[(size_t)(t + 1) * BH + (size_t)n2 * 32 + pb] = h1;  // direct publish
            outbuf[(size_t)t * BH + (size_t)pb * 1024 + n2] = h1;
        }
        __syncthreads();   // h stores issued by all threads before the arrive

        if (t < 511) {
            if (tid < 256) {  // prefetch gx(t+1): latency hides under the barrier
                const float* gxr = g_gx + ((size_t)(t + 1) * 32 + pb) * 4096;
                pg0 = gxr[n2]; pg1 = gxr[1024 + n2]; pg2 = gxr[2048 + n2]; pg3 = gxr[3072 + n2];
            }
            if (tid == 0) {   // 2-level arrive tree + root poll
                unsigned step = baseStep + (unsigned)(t + 1);
                red_release(&g_grp[grp * 32]);
                if (leader) {
                    while (ld_acquire(&g_grp[grp * 32]) < 16u * step) { }
                    red_release(&g_root);
                }
                while (ld_acquire(&g_root) < 8u * step) { }
            }
            __syncthreads();
        }
    }
    if (tid < 256) g_c[layer][pb * 1024 + n2] = c;
}

// ================= tail: (h_stack, c_stack) =================
__global__ void finalize(float* __restrict__ dout) {
    int idx = blockIdx.x * 256 + threadIdx.x;
    if (idx >= 4 * BH) return;
    int sec = idx >> 15, j = idx & 32767;
    float v;
    if (sec == 0)      v = g_out0[(size_t)511 * BH + j];
    else if (sec == 1) v = dout[(size_t)511 * BH + j];
    else               v = g_c[sec - 2][j];
    dout[OUTMAIN + idx] = v;
}

extern "C" void kernel_launch(void* const* d_in, const int* in_sizes, int n_in,
                              void* d_out, int out_size) {
    (void)in_sizes; (void)n_in; (void)out_size;
    const float* x    = (const float*)d_in[0];
    const float* Wih0 = (const float*)d_in[1];
    const float* Whh0 = (const float*)d_in[2];
    const float* bih0 = (const float*)d_in[3];
    const float* bhh0 = (const float*)d_in[4];
    const float* Wih1 = (const float*)d_in[5];
    const float* Whh1 = (const float*)d_in[6];
    const float* bih1 = (const float*)d_in[7];
    const float* bhh1 = (const float*)d_in[8];
    float* out = (float*)d_out;

    const int smemBytes = 32 * WROW * 4 + 16 * 256 * 16;  // 147968
    cudaFuncSetAttribute(lstm_persist, cudaFuncAttributeMaxDynamicSharedMemorySize, smemBytes);

    dim3 ggrid(32, 128);
    zero_cnt<<<1, 32>>>();
    gx_gemm<<<ggrid, 256>>>(x, Wih0, bih0, bhh0, 1);
    lstm_persist<<<128, 512, smemBytes>>>(out, Whh0, 0, 0u);
    gx_gemm<<<ggrid, 256>>>(nullptr, Wih1, bih1, bhh1, 0);
    lstm_persist<<<128, 512, smemBytes>>>(out, Whh1, 1, 511u);
    finalize<<<512, 256>>>(out);
}